// round 4
// baseline (speedup 1.0000x reference)
#include <cuda_runtime.h>
#include <cuda_bf16.h>
#include <cuda_fp8.h>
#include <cstdint>
#include <math.h>

#define DEV __device__ __forceinline__

// ---------------------------------------------------------------------------
// Problem constants
// ---------------------------------------------------------------------------
static constexpr int M_TOTAL = 16384;   // B*S
static constexpr int N_TOTAL = 2048;    // OUT
static constexpr int K_TOTAL = 2048;    // IN

static constexpr int BM = 128;
static constexpr int BN = 128;
static constexpr int BK = 64;                    // bf16 elems per K-chunk (128 B rows)
static constexpr int NUM_CHUNKS = K_TOTAL / BK;  // 32
static constexpr int STAGES = 3;
static constexpr int RS = 144;                   // padded row stride bytes
static constexpr int B_OFF = BM * RS;            // 18432
static constexpr int STAGE_BYTES = (BM + BN) * RS;      // 36864
static constexpr int SMEM_DYN = STAGES * STAGE_BYTES;   // 110592

// ---------------------------------------------------------------------------
// Scratch: e4m3 code values stored exactly as bf16.
// bf16 MMA on code values + fp32 scale in epilogue == exact fp8 GEMM.
// ---------------------------------------------------------------------------
__device__ __nv_bfloat16 g_A[(size_t)M_TOTAL * K_TOTAL];   // 64 MB
__device__ __nv_bfloat16 g_B[(size_t)N_TOTAL * K_TOTAL];   // 8 MB
__device__ int g_mode;   // qweight dtype: 0 = f32 codes, 1 = bf16 codes, 2 = raw e4m3 bytes

// ---------------------------------------------------------------------------
// PTX helpers (sm_80-safe subset only — compute_103 has no tcgen05)
// ---------------------------------------------------------------------------
DEV uint32_t smem_u32(const void* p) {
    uint32_t a;
    asm("{ .reg .u64 t; cvta.to.shared.u64 t, %1; cvt.u32.u64 %0, t; }" : "=r"(a) : "l"(p));
    return a;
}

#define LDSM_X4(r0, r1, r2, r3, addr) \
    asm volatile("ldmatrix.sync.aligned.m8n8.x4.shared.b16 {%0,%1,%2,%3}, [%4];" \
                 : "=r"(r0), "=r"(r1), "=r"(r2), "=r"(r3) : "r"(addr))

#define LDSM_X2(r0, r1, addr) \
    asm volatile("ldmatrix.sync.aligned.m8n8.x2.shared.b16 {%0,%1}, [%2];" \
                 : "=r"(r0), "=r"(r1) : "r"(addr))

#define MMA_BF16(c, a, b) \
    asm volatile("mma.sync.aligned.m16n8k16.row.col.f32.bf16.bf16.f32 " \
                 "{%0,%1,%2,%3}, {%4,%5,%6,%7}, {%8,%9}, {%0,%1,%2,%3};" \
                 : "+f"((c)[0]), "+f"((c)[1]), "+f"((c)[2]), "+f"((c)[3]) \
                 : "r"((a)[0]), "r"((a)[1]), "r"((a)[2]), "r"((a)[3]), \
                   "r"((b)[0]), "r"((b)[1]))

#define CP_ASYNC_16(dst, src) \
    asm volatile("cp.async.cg.shared.global [%0], [%1], 16;" :: "r"(dst), "l"(src))

DEV unsigned short code_to_bf16(float code) {
    return __bfloat16_as_ushort(__float2bfloat16(code));   // exact: e4m3 subset of bf16
}

DEV bool e4m3_exact(float v) {
    if (!isfinite(v) || fabsf(v) > 448.0f) return false;
    __nv_fp8_e4m3 e(v);
    return (float)e == v;
}

// ---------------------------------------------------------------------------
// Kernel 0: probe qweight dtype (256 threads, 1024 f32 slots / 2048 bf16 slots)
// NOTE: valid f32 codes ALSO pass the bf16 test (hi/lo halves decode as code/0),
// so f32 must be tested first. Random bytes fail both -> mode 2.
// ---------------------------------------------------------------------------
__global__ void fp8lin_detect(const void* qw) {
    __shared__ int ok32s, okbfs;
    const int t = threadIdx.x;
    if (t == 0) { ok32s = 1; okbfs = 1; }
    __syncthreads();

    const float* f = (const float*)qw;
    const unsigned short* hb = (const unsigned short*)qw;
    bool ok32 = true, okbf = true;
#pragma unroll
    for (int j = 0; j < 4; j++)
        if (!e4m3_exact(f[t * 4 + j])) ok32 = false;
#pragma unroll
    for (int j = 0; j < 8; j++)
        if (!e4m3_exact(__bfloat162float(__ushort_as_bfloat16(hb[t * 8 + j])))) okbf = false;

    if (!ok32) ok32s = 0;    // benign race: all writers store 0
    if (!okbf) okbfs = 0;
    __syncthreads();
    if (t == 0) g_mode = ok32s ? 0 : (okbfs ? 1 : 2);
}

// ---------------------------------------------------------------------------
// Kernel 1: x -> e4m3 code -> bf16 code (exact), 16 elems/thread
// ---------------------------------------------------------------------------
__global__ void __launch_bounds__(256) fp8lin_quant(const float* __restrict__ x,
                                                    const float* __restrict__ in_scale) {
    const float r = 1.0f / __ldg(in_scale);
    const size_t i = ((size_t)blockIdx.x * blockDim.x + threadIdx.x) * 16;
    const float4* src = reinterpret_cast<const float4*>(x + i);

    unsigned short h[16];
#pragma unroll
    for (int j = 0; j < 4; j++) {
        float4 v = src[j];
        float f[4] = {v.x * r, v.y * r, v.z * r, v.w * r};
#pragma unroll
        for (int q = 0; q < 4; q++) {
            __nv_fp8_e4m3 e(f[q]);                 // rn + satfinite == clip + cast
            h[4 * j + q] = code_to_bf16((float)e);
        }
    }
    uint4 o[2];
    uint32_t* ow = reinterpret_cast<uint32_t*>(o);
#pragma unroll
    for (int q = 0; q < 8; q++)
        ow[q] = (uint32_t)h[2 * q] | ((uint32_t)h[2 * q + 1] << 16);
    uint4* dst = reinterpret_cast<uint4*>(&g_A[i]);
    dst[0] = o[0];
    dst[1] = o[1];
}

// ---------------------------------------------------------------------------
// Kernel 2: qweight (any of 3 dtypes) -> bf16 codes, 8 elems/thread
// ---------------------------------------------------------------------------
__global__ void __launch_bounds__(256) fp8lin_wconv(const void* __restrict__ qw) {
    const int mode = g_mode;
    const size_t i = ((size_t)blockIdx.x * blockDim.x + threadIdx.x) * 8;

    uint4 o;
    if (mode == 0) {                       // float32 code values (expected path)
        const float4* s = reinterpret_cast<const float4*>((const float*)qw + i);
        float4 v0 = s[0], v1 = s[1];
        float f[8] = {v0.x, v0.y, v0.z, v0.w, v1.x, v1.y, v1.z, v1.w};
        unsigned short u[8];
#pragma unroll
        for (int j = 0; j < 8; j++) u[j] = code_to_bf16(f[j]);
        o.x = (uint32_t)u[0] | ((uint32_t)u[1] << 16);
        o.y = (uint32_t)u[2] | ((uint32_t)u[3] << 16);
        o.z = (uint32_t)u[4] | ((uint32_t)u[5] << 16);
        o.w = (uint32_t)u[6] | ((uint32_t)u[7] << 16);
    } else if (mode == 1) {                // already bf16 codes: straight copy
        o = *reinterpret_cast<const uint4*>((const unsigned short*)qw + i);
    } else {                               // raw e4m3 bytes
        uint2 raw = *reinterpret_cast<const uint2*>((const uint8_t*)qw + i);
        unsigned short u[8];
#pragma unroll
        for (int j = 0; j < 8; j++) {
            uint32_t word = (j < 4) ? raw.x : raw.y;
            __nv_fp8_e4m3 f;
            f.__x = (__nv_fp8_storage_t)((word >> ((j & 3) * 8)) & 0xFF);
            u[j] = code_to_bf16((float)f);
        }
        o.x = (uint32_t)u[0] | ((uint32_t)u[1] << 16);
        o.y = (uint32_t)u[2] | ((uint32_t)u[3] << 16);
        o.z = (uint32_t)u[4] | ((uint32_t)u[5] << 16);
        o.w = (uint32_t)u[6] | ((uint32_t)u[7] << 16);
    }
    *reinterpret_cast<uint4*>(&g_B[i]) = o;
}

// ---------------------------------------------------------------------------
// Kernel 3: bf16 HMMA GEMM, 128x128 tile, BK=64, 3-stage cp.async pipeline
// ---------------------------------------------------------------------------
DEV void load_stage(uint32_t sbase, const __nv_bfloat16* gA, const __nv_bfloat16* gB,
                    int k0, int tid) {
#pragma unroll
    for (int i = 0; i < 8; i++) {
        int c = tid + i * 256;              // 0..2047
        int row = (c >> 3) & 127;
        int seg = c & 7;
        const __nv_bfloat16* src = ((c < 1024) ? gA : gB)
                                 + (size_t)row * K_TOTAL + k0 + seg * 8;
        uint32_t dst = sbase + ((c < 1024) ? 0u : (uint32_t)B_OFF)
                     + (uint32_t)(row * RS + seg * 16);
        CP_ASYNC_16(dst, src);
    }
}

__global__ void __launch_bounds__(256, 1) fp8lin_gemm(float* __restrict__ out,
                                                      const float* __restrict__ in_scale,
                                                      const float* __restrict__ w_scale,
                                                      const float* __restrict__ bias) {
    extern __shared__ char dsm[];
    const uint32_t smem0 = smem_u32(dsm);

    const int tid = threadIdx.x;
    const int wid = tid >> 5;
    const int lane = tid & 31;
    const int warp_m = wid >> 2;        // 0..1 -> 64 rows
    const int warp_n = wid & 3;         // 0..3 -> 32 cols

    const int n0 = blockIdx.x * BN;     // N fastest -> A-tile L2 reuse
    const int m0 = blockIdx.y * BM;

    const __nv_bfloat16* gA = g_A + (size_t)m0 * K_TOTAL;
    const __nv_bfloat16* gB = g_B + (size_t)n0 * K_TOTAL;

    // A x4: mat = lane>>3; row = (mat&1)*8 + (lane&7); k-byte = (mat>>1)*16
    const int amat = lane >> 3;
    const uint32_t a_base = (uint32_t)((warp_m * 64 + (amat & 1) * 8 + (lane & 7)) * RS
                                       + (amat >> 1) * 16);
    // B x2: l2 = lane&15; n = l2&7; k-byte = (l2>>3)*16
    const int l2 = lane & 15;
    const uint32_t b_base = (uint32_t)(B_OFF + (warp_n * 32 + (l2 & 7)) * RS
                                       + (l2 >> 3) * 16);

    float acc[4][4][4];
#pragma unroll
    for (int mt = 0; mt < 4; mt++)
#pragma unroll
        for (int nt = 0; nt < 4; nt++)
#pragma unroll
            for (int q = 0; q < 4; q++) acc[mt][nt][q] = 0.0f;

#pragma unroll
    for (int c = 0; c < STAGES - 1; c++) {
        load_stage(smem0 + c * STAGE_BYTES, gA, gB, c * BK, tid);
        asm volatile("cp.async.commit_group;");
    }

    for (int c = 0; c < NUM_CHUNKS; c++) {
        asm volatile("cp.async.wait_group %0;" :: "n"(STAGES - 2));
        __syncthreads();

        const int nc = c + STAGES - 1;
        if (nc < NUM_CHUNKS)
            load_stage(smem0 + (nc % STAGES) * STAGE_BYTES, gA, gB, nc * BK, tid);
        asm volatile("cp.async.commit_group;");

        const uint32_t sb = smem0 + (c % STAGES) * STAGE_BYTES;
#pragma unroll
        for (int ks = 0; ks < 4; ks++) {        // 4 x k16 per 64-elem chunk
            uint32_t a[4][4], b[4][2];
#pragma unroll
            for (int mt = 0; mt < 4; mt++)
                LDSM_X4(a[mt][0], a[mt][1], a[mt][2], a[mt][3],
                        sb + a_base + (uint32_t)(mt * 16 * RS + ks * 32));
#pragma unroll
            for (int nt = 0; nt < 4; nt++)
                LDSM_X2(b[nt][0], b[nt][1],
                        sb + b_base + (uint32_t)(nt * 8 * RS + ks * 32));
#pragma unroll
            for (int mt = 0; mt < 4; mt++)
#pragma unroll
                for (int nt = 0; nt < 4; nt++)
                    MMA_BF16(acc[mt][nt], a[mt], b[nt]);
        }
    }

    // ---------------- Epilogue: dequant scale + bias ----------------
    const float sc = __ldg(in_scale) * __ldg(w_scale);
    const int gid = lane >> 2;
    const int tig = lane & 3;

    float2 bv[4];
#pragma unroll
    for (int nt = 0; nt < 4; nt++)
        bv[nt] = *reinterpret_cast<const float2*>(bias + n0 + warp_n * 32 + nt * 8 + 2 * tig);

#pragma unroll
    for (int mt = 0; mt < 4; mt++) {
        const int row = m0 + warp_m * 64 + mt * 16 + gid;
#pragma unroll
        for (int nt = 0; nt < 4; nt++) {
            const int col = n0 + warp_n * 32 + nt * 8 + 2 * tig;
            float2 o0, o1;
            o0.x = acc[mt][nt][0] * sc + bv[nt].x;
            o0.y = acc[mt][nt][1] * sc + bv[nt].y;
            o1.x = acc[mt][nt][2] * sc + bv[nt].x;
            o1.y = acc[mt][nt][3] * sc + bv[nt].y;
            *reinterpret_cast<float2*>(out + (size_t)row * N_TOTAL + col) = o0;
            *reinterpret_cast<float2*>(out + (size_t)(row + 8) * N_TOTAL + col) = o1;
        }
    }
}

// ---------------------------------------------------------------------------
// Launch — inputs identified by element count; scales by dict order (x first)
// ---------------------------------------------------------------------------
extern "C" void kernel_launch(void* const* d_in, const int* in_sizes, int n_in,
                              void* d_out, int out_size) {
    const float* x = nullptr;
    const void* qweight = nullptr;
    const float* bias = nullptr;
    const float* s_first = nullptr;
    const float* s_second = nullptr;
    int x_idx = -1;

    for (int i = 0; i < n_in; i++) {
        long long sz = in_sizes[i];
        if (sz == (long long)M_TOTAL * K_TOTAL) { x = (const float*)d_in[i]; x_idx = i; }
        else if (sz == (long long)N_TOTAL * K_TOTAL) qweight = d_in[i];
        else if (sz == N_TOTAL) bias = (const float*)d_in[i];
        else if (sz == 1) { if (!s_first) s_first = (const float*)d_in[i];
                            else s_second = (const float*)d_in[i]; }
    }
    const float* wscale = (x_idx == 0) ? s_first : s_second;
    const float* iscale = (x_idx == 0) ? s_second : s_first;
    float* out = (float*)d_out;

    fp8lin_detect<<<1, 256>>>(qweight);
    const size_t total = (size_t)M_TOTAL * K_TOTAL;
    fp8lin_quant<<<(unsigned)(total / (16 * 256)), 256>>>(x, iscale);
    fp8lin_wconv<<<(unsigned)((size_t)N_TOTAL * K_TOTAL / (8 * 256)), 256>>>(qweight);

    cudaFuncSetAttribute(fp8lin_gemm, cudaFuncAttributeMaxDynamicSharedMemorySize, SMEM_DYN);
    dim3 grid(N_TOTAL / BN, M_TOTAL / BM);
    fp8lin_gemm<<<grid, 256, SMEM_DYN>>>(out, iscale, wscale, bias);
}

// round 5
// speedup vs baseline: 1.1595x; 1.1595x over previous
#include <cuda_runtime.h>
#include <cuda_bf16.h>
#include <cuda_fp8.h>
#include <cstdint>
#include <math.h>

#define DEV __device__ __forceinline__

// ---------------------------------------------------------------------------
// Problem constants
// ---------------------------------------------------------------------------
static constexpr int M_TOTAL = 16384;   // B*S
static constexpr int N_TOTAL = 2048;    // OUT
static constexpr int K_TOTAL = 2048;    // IN

static constexpr int BM = 128;
static constexpr int BN = 128;
static constexpr int BK = 64;                    // fp8 bytes per K-chunk (64 B rows)
static constexpr int NUM_CHUNKS = K_TOTAL / BK;  // 32
static constexpr int STAGES = 4;
static constexpr int RS = 80;                    // padded row stride (64 data + 16)
static constexpr int B_OFF = BM * RS;            // 10240
static constexpr int STAGE_BYTES = (BM + BN) * RS;      // 20480
static constexpr int SMEM_DYN = STAGES * STAGE_BYTES;   // 81920 -> 2 CTAs/SM fits

// ---------------------------------------------------------------------------
// Scratch: e4m3 bytes for A (quantized x) and B (weight codes)
// ---------------------------------------------------------------------------
__device__ uint8_t g_A[(size_t)M_TOTAL * K_TOTAL];   // 32 MB
__device__ uint8_t g_B[(size_t)N_TOTAL * K_TOTAL];   // 4 MB
__device__ int g_mode;   // qweight dtype: 0 = f32 codes, 1 = bf16 codes, 2 = raw bytes

// ---------------------------------------------------------------------------
// PTX helpers (sm_80/sm_89 subset — compute_103 has no tcgen05)
// ---------------------------------------------------------------------------
DEV uint32_t smem_u32(const void* p) {
    uint32_t a;
    asm("{ .reg .u64 t; cvta.to.shared.u64 t, %1; cvt.u32.u64 %0, t; }" : "=r"(a) : "l"(p));
    return a;
}

#define LDSM_X4(r0, r1, r2, r3, addr) \
    asm volatile("ldmatrix.sync.aligned.m8n8.x4.shared.b16 {%0,%1,%2,%3}, [%4];" \
                 : "=r"(r0), "=r"(r1), "=r"(r2), "=r"(r3) : "r"(addr))

#define LDSM_X2(r0, r1, addr) \
    asm volatile("ldmatrix.sync.aligned.m8n8.x2.shared.b16 {%0,%1}, [%2];" \
                 : "=r"(r0), "=r"(r1) : "r"(addr))

// fp8 e4m3 MMA, fragment layout (b32 = 4 consecutive k-bytes of one row):
//  A (16x32): a0=(row g, k 4t..+3) a1=(g+8, same) a2=(g, k16+4t..+3) a3=(g+8, k16+..)
//  B (32x8 col-major == [n,k] row-major): b0=(k 4t..+3, col g) b1=(k16+4t..+3, col g)
#define MMA_E4M3(c, a, b) \
    asm volatile("mma.sync.aligned.m16n8k32.row.col.f32.e4m3.e4m3.f32 " \
                 "{%0,%1,%2,%3}, {%4,%5,%6,%7}, {%8,%9}, {%0,%1,%2,%3};" \
                 : "+f"((c)[0]), "+f"((c)[1]), "+f"((c)[2]), "+f"((c)[3]) \
                 : "r"((a)[0]), "r"((a)[1]), "r"((a)[2]), "r"((a)[3]), \
                   "r"((b)[0]), "r"((b)[1]))

#define CP_ASYNC_16(dst, src) \
    asm volatile("cp.async.cg.shared.global [%0], [%1], 16;" :: "r"(dst), "l"(src))

DEV bool e4m3_exact(float v) {
    if (!isfinite(v) || fabsf(v) > 448.0f) return false;
    __nv_fp8_e4m3 e(v);
    return (float)e == v;
}

// ---------------------------------------------------------------------------
// Kernel 0: probe qweight dtype (f32 must be tested before bf16)
// ---------------------------------------------------------------------------
__global__ void fp8lin_detect(const void* qw) {
    __shared__ int ok32s, okbfs;
    const int t = threadIdx.x;
    if (t == 0) { ok32s = 1; okbfs = 1; }
    __syncthreads();

    const float* f = (const float*)qw;
    const unsigned short* hb = (const unsigned short*)qw;
    bool ok32 = true, okbf = true;
#pragma unroll
    for (int j = 0; j < 4; j++)
        if (!e4m3_exact(f[t * 4 + j])) ok32 = false;
#pragma unroll
    for (int j = 0; j < 8; j++)
        if (!e4m3_exact(__bfloat162float(__ushort_as_bfloat16(hb[t * 8 + j])))) okbf = false;

    if (!ok32) ok32s = 0;
    if (!okbf) okbfs = 0;
    __syncthreads();
    if (t == 0) g_mode = ok32s ? 0 : (okbfs ? 1 : 2);
}

// ---------------------------------------------------------------------------
// Kernel 1: x -> e4m3 bytes, 16 elems/thread (16 B out)
// ---------------------------------------------------------------------------
__global__ void __launch_bounds__(256) fp8lin_quant(const float* __restrict__ x,
                                                    const float* __restrict__ in_scale) {
    const float r = 1.0f / __ldg(in_scale);
    const size_t i = ((size_t)blockIdx.x * blockDim.x + threadIdx.x) * 16;
    const float4* src = reinterpret_cast<const float4*>(x + i);

    unsigned short h[8];
#pragma unroll
    for (int j = 0; j < 4; j++) {
        float4 v = src[j];
        float2 p0 = make_float2(v.x * r, v.y * r);
        float2 p1 = make_float2(v.z * r, v.w * r);
        h[2 * j + 0] = (unsigned short)__nv_cvt_float2_to_fp8x2(p0, __NV_SATFINITE, __NV_E4M3);
        h[2 * j + 1] = (unsigned short)__nv_cvt_float2_to_fp8x2(p1, __NV_SATFINITE, __NV_E4M3);
    }
    uint4 o;
    o.x = (uint32_t)h[0] | ((uint32_t)h[1] << 16);
    o.y = (uint32_t)h[2] | ((uint32_t)h[3] << 16);
    o.z = (uint32_t)h[4] | ((uint32_t)h[5] << 16);
    o.w = (uint32_t)h[6] | ((uint32_t)h[7] << 16);
    *reinterpret_cast<uint4*>(&g_A[i]) = o;
}

// ---------------------------------------------------------------------------
// Kernel 2: qweight (f32 codes / bf16 codes / raw bytes) -> e4m3 bytes
// 16 codes per thread. Codes are exact e4m3 values: rn+satfinite is identity.
// ---------------------------------------------------------------------------
__global__ void __launch_bounds__(256) fp8lin_wconv(const void* __restrict__ qw) {
    const int mode = g_mode;
    const size_t i = ((size_t)blockIdx.x * blockDim.x + threadIdx.x) * 16;

    uint4 o;
    if (mode == 0) {                       // float32 code values (expected)
        const float4* s = reinterpret_cast<const float4*>((const float*)qw + i);
        unsigned short h[8];
#pragma unroll
        for (int j = 0; j < 4; j++) {
            float4 v = s[j];
            float2 p0 = make_float2(v.x, v.y);
            float2 p1 = make_float2(v.z, v.w);
            h[2 * j + 0] = (unsigned short)__nv_cvt_float2_to_fp8x2(p0, __NV_SATFINITE, __NV_E4M3);
            h[2 * j + 1] = (unsigned short)__nv_cvt_float2_to_fp8x2(p1, __NV_SATFINITE, __NV_E4M3);
        }
        o.x = (uint32_t)h[0] | ((uint32_t)h[1] << 16);
        o.y = (uint32_t)h[2] | ((uint32_t)h[3] << 16);
        o.z = (uint32_t)h[4] | ((uint32_t)h[5] << 16);
        o.w = (uint32_t)h[6] | ((uint32_t)h[7] << 16);
    } else if (mode == 2) {                // already raw e4m3 bytes
        o = *reinterpret_cast<const uint4*>((const uint8_t*)qw + i);
    } else {                               // bf16 codes
        const unsigned short* s = (const unsigned short*)qw + i;
        unsigned short h[8];
#pragma unroll
        for (int j = 0; j < 8; j++) {
            float2 p = make_float2(__bfloat162float(__ushort_as_bfloat16(s[2 * j])),
                                   __bfloat162float(__ushort_as_bfloat16(s[2 * j + 1])));
            h[j] = (unsigned short)__nv_cvt_float2_to_fp8x2(p, __NV_SATFINITE, __NV_E4M3);
        }
        o.x = (uint32_t)h[0] | ((uint32_t)h[1] << 16);
        o.y = (uint32_t)h[2] | ((uint32_t)h[3] << 16);
        o.z = (uint32_t)h[4] | ((uint32_t)h[5] << 16);
        o.w = (uint32_t)h[6] | ((uint32_t)h[7] << 16);
    }
    *reinterpret_cast<uint4*>(&g_B[i]) = o;
}

// ---------------------------------------------------------------------------
// Kernel 3: fp8 QMMA GEMM, 128x128 tile, BK=64, 4-stage cp.async, 2 CTAs/SM
// ---------------------------------------------------------------------------
DEV void load_stage(uint32_t sbase, const uint8_t* gA, const uint8_t* gB,
                    int k0, int tid) {
    // 1024 x 16B segments: A = 128 rows x 4 segs, then B = 128 rows x 4 segs.
#pragma unroll
    for (int i = 0; i < 4; i++) {
        int c = tid + i * 256;              // 0..1023
        int row = (c >> 2) & 127;
        int seg = c & 3;
        const uint8_t* src = ((c < 512) ? gA : gB) + (size_t)row * K_TOTAL + k0 + seg * 16;
        uint32_t dst = sbase + ((c < 512) ? 0u : (uint32_t)B_OFF)
                     + (uint32_t)(row * RS + seg * 16);
        CP_ASYNC_16(dst, src);
    }
}

__global__ void __launch_bounds__(256, 2) fp8lin_gemm(float* __restrict__ out,
                                                      const float* __restrict__ in_scale,
                                                      const float* __restrict__ w_scale,
                                                      const float* __restrict__ bias) {
    extern __shared__ char dsm[];
    const uint32_t smem0 = smem_u32(dsm);

    const int tid = threadIdx.x;
    const int wid = tid >> 5;
    const int lane = tid & 31;
    const int warp_m = wid >> 2;        // 0..1 -> 64 rows
    const int warp_n = wid & 3;         // 0..3 -> 32 cols

    const int n0 = blockIdx.x * BN;     // N fastest -> A-tile L2 reuse
    const int m0 = blockIdx.y * BM;

    const uint8_t* gA = g_A + (size_t)m0 * K_TOTAL;
    const uint8_t* gB = g_B + (size_t)n0 * K_TOTAL;

    // A x4: mat = lane>>3; row = (mat&1)*8 + (lane&7); k-byte = (mat>>1)*16
    const int amat = lane >> 3;
    const uint32_t a_base = (uint32_t)((warp_m * 64 + (amat & 1) * 8 + (lane & 7)) * RS
                                       + (amat >> 1) * 16);
    // B x2: l2 = lane&15; n = l2&7; k-byte = (l2>>3)*16
    const int l2 = lane & 15;
    const uint32_t b_base = (uint32_t)(B_OFF + (warp_n * 32 + (l2 & 7)) * RS
                                       + (l2 >> 3) * 16);

    float acc[4][4][4];
#pragma unroll
    for (int mt = 0; mt < 4; mt++)
#pragma unroll
        for (int nt = 0; nt < 4; nt++)
#pragma unroll
            for (int q = 0; q < 4; q++) acc[mt][nt][q] = 0.0f;

#pragma unroll
    for (int c = 0; c < STAGES - 1; c++) {
        load_stage(smem0 + c * STAGE_BYTES, gA, gB, c * BK, tid);
        asm volatile("cp.async.commit_group;");
    }

    for (int c = 0; c < NUM_CHUNKS; c++) {
        asm volatile("cp.async.wait_group %0;" :: "n"(STAGES - 2));
        __syncthreads();

        const int nc = c + STAGES - 1;
        if (nc < NUM_CHUNKS)
            load_stage(smem0 + (nc % STAGES) * STAGE_BYTES, gA, gB, nc * BK, tid);
        asm volatile("cp.async.commit_group;");

        const uint32_t sb = smem0 + (c % STAGES) * STAGE_BYTES;
#pragma unroll
        for (int ks = 0; ks < 2; ks++) {        // 2 x k32 per 64-byte chunk
            uint32_t a[4][4], b[4][2];
#pragma unroll
            for (int mt = 0; mt < 4; mt++)
                LDSM_X4(a[mt][0], a[mt][1], a[mt][2], a[mt][3],
                        sb + a_base + (uint32_t)(mt * 16 * RS + ks * 32));
#pragma unroll
            for (int nt = 0; nt < 4; nt++)
                LDSM_X2(b[nt][0], b[nt][1],
                        sb + b_base + (uint32_t)(nt * 8 * RS + ks * 32));
#pragma unroll
            for (int mt = 0; mt < 4; mt++)
#pragma unroll
                for (int nt = 0; nt < 4; nt++)
                    MMA_E4M3(acc[mt][nt], a[mt], b[nt]);
        }
    }

    // ---------------- Epilogue: dequant scale + bias ----------------
    const float sc = __ldg(in_scale) * __ldg(w_scale);
    const int gid = lane >> 2;
    const int tig = lane & 3;

    float2 bv[4];
#pragma unroll
    for (int nt = 0; nt < 4; nt++)
        bv[nt] = *reinterpret_cast<const float2*>(bias + n0 + warp_n * 32 + nt * 8 + 2 * tig);

#pragma unroll
    for (int mt = 0; mt < 4; mt++) {
        const int row = m0 + warp_m * 64 + mt * 16 + gid;
#pragma unroll
        for (int nt = 0; nt < 4; nt++) {
            const int col = n0 + warp_n * 32 + nt * 8 + 2 * tig;
            float2 o0, o1;
            o0.x = acc[mt][nt][0] * sc + bv[nt].x;
            o0.y = acc[mt][nt][1] * sc + bv[nt].y;
            o1.x = acc[mt][nt][2] * sc + bv[nt].x;
            o1.y = acc[mt][nt][3] * sc + bv[nt].y;
            *reinterpret_cast<float2*>(out + (size_t)row * N_TOTAL + col) = o0;
            *reinterpret_cast<float2*>(out + (size_t)(row + 8) * N_TOTAL + col) = o1;
        }
    }
}

// ---------------------------------------------------------------------------
// Launch — inputs identified by element count; scales by dict order (x first)
// ---------------------------------------------------------------------------
extern "C" void kernel_launch(void* const* d_in, const int* in_sizes, int n_in,
                              void* d_out, int out_size) {
    const float* x = nullptr;
    const void* qweight = nullptr;
    const float* bias = nullptr;
    const float* s_first = nullptr;
    const float* s_second = nullptr;
    int x_idx = -1;

    for (int i = 0; i < n_in; i++) {
        long long sz = in_sizes[i];
        if (sz == (long long)M_TOTAL * K_TOTAL) { x = (const float*)d_in[i]; x_idx = i; }
        else if (sz == (long long)N_TOTAL * K_TOTAL) qweight = d_in[i];
        else if (sz == N_TOTAL) bias = (const float*)d_in[i];
        else if (sz == 1) { if (!s_first) s_first = (const float*)d_in[i];
                            else s_second = (const float*)d_in[i]; }
    }
    const float* wscale = (x_idx == 0) ? s_first : s_second;
    const float* iscale = (x_idx == 0) ? s_second : s_first;
    float* out = (float*)d_out;

    fp8lin_detect<<<1, 256>>>(qweight);
    const size_t total = (size_t)M_TOTAL * K_TOTAL;
    fp8lin_quant<<<(unsigned)(total / (16 * 256)), 256>>>(x, iscale);
    fp8lin_wconv<<<(unsigned)((size_t)N_TOTAL * K_TOTAL / (16 * 256)), 256>>>(qweight);

    cudaFuncSetAttribute(fp8lin_gemm, cudaFuncAttributeMaxDynamicSharedMemorySize, SMEM_DYN);
    dim3 grid(N_TOTAL / BN, M_TOTAL / BM);
    fp8lin_gemm<<<grid, 256, SMEM_DYN>>>(out, iscale, wscale, bias);
}

// round 6
// speedup vs baseline: 1.2187x; 1.0511x over previous
#include <cuda_runtime.h>
#include <cuda_bf16.h>
#include <cuda_fp8.h>
#include <cstdint>
#include <math.h>

#define DEV __device__ __forceinline__

// ---------------------------------------------------------------------------
// Problem constants
// ---------------------------------------------------------------------------
static constexpr int M_TOTAL = 16384;   // B*S
static constexpr int N_TOTAL = 2048;    // OUT
static constexpr int K_TOTAL = 2048;    // IN

static constexpr int BM = 128;
static constexpr int BN = 128;
static constexpr int BK = 64;                    // fp8 bytes per K-chunk
static constexpr int NUM_CHUNKS = K_TOTAL / BK;  // 32
static constexpr int STAGES = 4;
static constexpr int RS = 80;                    // padded row stride
static constexpr int B_OFF = BM * RS;            // 10240
static constexpr int STAGE_BYTES = (BM + BN) * RS;      // 20480
static constexpr int SMEM_DYN = STAGES * STAGE_BYTES;   // 81920 -> 2 CTAs/SM

// ---------------------------------------------------------------------------
// Scratch
// ---------------------------------------------------------------------------
__device__ uint8_t g_A[(size_t)M_TOTAL * K_TOTAL];   // 32 MB
__device__ uint8_t g_B[(size_t)N_TOTAL * K_TOTAL];   // 4 MB
__device__ int g_mode;   // qweight dtype: 0 = f32 codes, 1 = bf16 codes, 2 = raw bytes

// ---------------------------------------------------------------------------
// PTX helpers
// ---------------------------------------------------------------------------
DEV uint32_t smem_u32(const void* p) {
    uint32_t a;
    asm("{ .reg .u64 t; cvta.to.shared.u64 t, %1; cvt.u32.u64 %0, t; }" : "=r"(a) : "l"(p));
    return a;
}

#define LDSM_X4(r0, r1, r2, r3, addr) \
    asm volatile("ldmatrix.sync.aligned.m8n8.x4.shared.b16 {%0,%1,%2,%3}, [%4];" \
                 : "=r"(r0), "=r"(r1), "=r"(r2), "=r"(r3) : "r"(addr))

// fp8 e4m3 MMA (validated in R5):
//  A: a0=(row g, k 4t..+3) a1=(g+8) a2=(g, k16+4t..+3) a3=(g+8, k16+..)
//  B: b0=(k 4t..+3, col g) b1=(k16+4t..+3, col g)
#define MMA_E4M3(c, a0, a1, a2, a3, b0, b1) \
    asm volatile("mma.sync.aligned.m16n8k32.row.col.f32.e4m3.e4m3.f32 " \
                 "{%0,%1,%2,%3}, {%4,%5,%6,%7}, {%8,%9}, {%0,%1,%2,%3};" \
                 : "+f"((c)[0]), "+f"((c)[1]), "+f"((c)[2]), "+f"((c)[3]) \
                 : "r"(a0), "r"(a1), "r"(a2), "r"(a3), "r"(b0), "r"(b1))

#define CP_ASYNC_16(dst, src) \
    asm volatile("cp.async.cg.shared.global [%0], [%1], 16;" :: "r"(dst), "l"(src))

DEV bool e4m3_exact(float v) {
    if (!isfinite(v) || fabsf(v) > 448.0f) return false;
    __nv_fp8_e4m3 e(v);
    return (float)e == v;
}

// ---------------------------------------------------------------------------
// Kernel 0: probe qweight dtype (f32 tested before bf16)
// ---------------------------------------------------------------------------
__global__ void fp8lin_detect(const void* qw) {
    __shared__ int ok32s, okbfs;
    const int t = threadIdx.x;
    if (t == 0) { ok32s = 1; okbfs = 1; }
    __syncthreads();

    const float* f = (const float*)qw;
    const unsigned short* hb = (const unsigned short*)qw;
    bool ok32 = true, okbf = true;
#pragma unroll
    for (int j = 0; j < 4; j++)
        if (!e4m3_exact(f[t * 4 + j])) ok32 = false;
#pragma unroll
    for (int j = 0; j < 8; j++)
        if (!e4m3_exact(__bfloat162float(__ushort_as_bfloat16(hb[t * 8 + j])))) okbf = false;

    if (!ok32) ok32s = 0;
    if (!okbf) okbfs = 0;
    __syncthreads();
    if (t == 0) g_mode = ok32s ? 0 : (okbfs ? 1 : 2);
}

// ---------------------------------------------------------------------------
// Kernel 1: x -> e4m3 bytes, 16 elems/thread
// ---------------------------------------------------------------------------
__global__ void __launch_bounds__(256) fp8lin_quant(const float* __restrict__ x,
                                                    const float* __restrict__ in_scale) {
    const float r = 1.0f / __ldg(in_scale);
    const size_t i = ((size_t)blockIdx.x * blockDim.x + threadIdx.x) * 16;
    const float4* src = reinterpret_cast<const float4*>(x + i);

    unsigned short h[8];
#pragma unroll
    for (int j = 0; j < 4; j++) {
        float4 v = src[j];
        float2 p0 = make_float2(v.x * r, v.y * r);
        float2 p1 = make_float2(v.z * r, v.w * r);
        h[2 * j + 0] = (unsigned short)__nv_cvt_float2_to_fp8x2(p0, __NV_SATFINITE, __NV_E4M3);
        h[2 * j + 1] = (unsigned short)__nv_cvt_float2_to_fp8x2(p1, __NV_SATFINITE, __NV_E4M3);
    }
    uint4 o;
    o.x = (uint32_t)h[0] | ((uint32_t)h[1] << 16);
    o.y = (uint32_t)h[2] | ((uint32_t)h[3] << 16);
    o.z = (uint32_t)h[4] | ((uint32_t)h[5] << 16);
    o.w = (uint32_t)h[6] | ((uint32_t)h[7] << 16);
    *reinterpret_cast<uint4*>(&g_A[i]) = o;
}

// ---------------------------------------------------------------------------
// Kernel 2: qweight -> e4m3 bytes (3 dtype modes)
// ---------------------------------------------------------------------------
__global__ void __launch_bounds__(256) fp8lin_wconv(const void* __restrict__ qw) {
    const int mode = g_mode;
    const size_t i = ((size_t)blockIdx.x * blockDim.x + threadIdx.x) * 16;

    uint4 o;
    if (mode == 0) {                       // float32 code values (expected)
        const float4* s = reinterpret_cast<const float4*>((const float*)qw + i);
        unsigned short h[8];
#pragma unroll
        for (int j = 0; j < 4; j++) {
            float4 v = s[j];
            float2 p0 = make_float2(v.x, v.y);
            float2 p1 = make_float2(v.z, v.w);
            h[2 * j + 0] = (unsigned short)__nv_cvt_float2_to_fp8x2(p0, __NV_SATFINITE, __NV_E4M3);
            h[2 * j + 1] = (unsigned short)__nv_cvt_float2_to_fp8x2(p1, __NV_SATFINITE, __NV_E4M3);
        }
        o.x = (uint32_t)h[0] | ((uint32_t)h[1] << 16);
        o.y = (uint32_t)h[2] | ((uint32_t)h[3] << 16);
        o.z = (uint32_t)h[4] | ((uint32_t)h[5] << 16);
        o.w = (uint32_t)h[6] | ((uint32_t)h[7] << 16);
    } else if (mode == 2) {                // raw e4m3 bytes
        o = *reinterpret_cast<const uint4*>((const uint8_t*)qw + i);
    } else {                               // bf16 codes
        const unsigned short* s = (const unsigned short*)qw + i;
        unsigned short h[8];
#pragma unroll
        for (int j = 0; j < 8; j++) {
            float2 p = make_float2(__bfloat162float(__ushort_as_bfloat16(s[2 * j])),
                                   __bfloat162float(__ushort_as_bfloat16(s[2 * j + 1])));
            h[j] = (unsigned short)__nv_cvt_float2_to_fp8x2(p, __NV_SATFINITE, __NV_E4M3);
        }
        o.x = (uint32_t)h[0] | ((uint32_t)h[1] << 16);
        o.y = (uint32_t)h[2] | ((uint32_t)h[3] << 16);
        o.z = (uint32_t)h[4] | ((uint32_t)h[5] << 16);
        o.w = (uint32_t)h[6] | ((uint32_t)h[7] << 16);
    }
    *reinterpret_cast<uint4*>(&g_B[i]) = o;
}

// ---------------------------------------------------------------------------
// Kernel 3: fp8 QMMA GEMM — stage-unrolled, hoisted addressing, B-LDSM x4
// ---------------------------------------------------------------------------
__global__ void __launch_bounds__(256, 2) fp8lin_gemm(float* __restrict__ out,
                                                      const float* __restrict__ in_scale,
                                                      const float* __restrict__ w_scale,
                                                      const float* __restrict__ bias) {
    extern __shared__ char dsm[];
    const uint32_t smem0 = smem_u32(dsm);

    const int tid = threadIdx.x;
    const int wid = tid >> 5;
    const int lane = tid & 31;
    const int warp_m = wid >> 2;        // 0..1 -> 64 rows
    const int warp_n = wid & 3;         // 0..3 -> 32 cols

    const int n0 = blockIdx.x * BN;     // N fastest -> A-tile L2 reuse
    const int m0 = blockIdx.y * BM;

    // ---- hoisted cp.async addressing: 4 src pointers, 4 const dst offsets ----
    const int ld_row = tid >> 2;        // 0..63
    const int ld_seg = tid & 3;
    const uint8_t* srcA0 = g_A + (size_t)(m0 + ld_row) * K_TOTAL + ld_seg * 16;
    const uint8_t* srcA1 = srcA0 + (size_t)64 * K_TOTAL;
    const uint8_t* srcB0 = g_B + (size_t)(n0 + ld_row) * K_TOTAL + ld_seg * 16;
    const uint8_t* srcB1 = srcB0 + (size_t)64 * K_TOTAL;
    const uint32_t dA0 = (uint32_t)(ld_row * RS + ld_seg * 16);
    const uint32_t dA1 = dA0 + 64 * RS;
    const uint32_t dB0 = dA0 + B_OFF;
    const uint32_t dB1 = dB0 + 64 * RS;

#define ISSUE_STAGE(stage_base) do { \
        CP_ASYNC_16((stage_base) + dA0, srcA0); \
        CP_ASYNC_16((stage_base) + dA1, srcA1); \
        CP_ASYNC_16((stage_base) + dB0, srcB0); \
        CP_ASYNC_16((stage_base) + dB1, srcB1); \
        srcA0 += BK; srcA1 += BK; srcB0 += BK; srcB1 += BK; \
        asm volatile("cp.async.commit_group;"); \
    } while (0)

    // ---- ldmatrix bases ----
    // A x4: mat = lane>>3; row = (mat&1)*8 + (lane&7); k-byte = (mat>>1)*16
    const int amat = lane >> 3;
    const uint32_t a_base = smem0
        + (uint32_t)((warp_m * 64 + (amat & 1) * 8 + (lane & 7)) * RS + (amat >> 1) * 16);
    // B x4 (two n-tiles per op): mats = (nt even, k0),(nt even, k16),(nt odd, k0),(nt odd, k16)
    // lane l: nt-sel = l>>4, k-half = (l>>3)&1, row = l&7
    const uint32_t b_base = smem0 + (uint32_t)(B_OFF
        + (warp_n * 32 + ((lane >> 4) * 8) + (lane & 7)) * RS + ((lane >> 3) & 1) * 16);

    float acc[4][4][4];
#pragma unroll
    for (int mt = 0; mt < 4; mt++)
#pragma unroll
        for (int nt = 0; nt < 4; nt++)
#pragma unroll
            for (int q = 0; q < 4; q++) acc[mt][nt][q] = 0.0f;

    // Prefill stages 0..2
    ISSUE_STAGE(smem0 + 0 * STAGE_BYTES);
    ISSUE_STAGE(smem0 + 1 * STAGE_BYTES);
    ISSUE_STAGE(smem0 + 2 * STAGE_BYTES);

#pragma unroll 1
    for (int cb = 0; cb < NUM_CHUNKS; cb += STAGES) {
#pragma unroll
        for (int u = 0; u < STAGES; u++) {
            const int c = cb + u;
            asm volatile("cp.async.wait_group %0;" :: "n"(STAGES - 2));
            __syncthreads();

            // prefetch chunk c+3 into stage (u+3)&3 — compile-time stage offset
            if (c + STAGES - 1 < NUM_CHUNKS) {
                ISSUE_STAGE(smem0 + (uint32_t)(((u + 3) & 3) * STAGE_BYTES));
            } else {
                asm volatile("cp.async.commit_group;");   // keep 1 commit / iter
            }

            const uint32_t soff = (uint32_t)(u * STAGE_BYTES);  // constant
#pragma unroll
            for (int ks = 0; ks < 2; ks++) {
                uint32_t a[4][4], b[4][2];
#pragma unroll
                for (int mt = 0; mt < 4; mt++)
                    LDSM_X4(a[mt][0], a[mt][1], a[mt][2], a[mt][3],
                            a_base + soff + (uint32_t)(mt * 16 * RS + ks * 32));
#pragma unroll
                for (int p = 0; p < 2; p++)   // each loads nt=2p and nt=2p+1
                    LDSM_X4(b[2 * p][0], b[2 * p][1], b[2 * p + 1][0], b[2 * p + 1][1],
                            b_base + soff + (uint32_t)(p * 16 * RS + ks * 32));
#pragma unroll
                for (int mt = 0; mt < 4; mt++)
#pragma unroll
                    for (int nt = 0; nt < 4; nt++)
                        MMA_E4M3(acc[mt][nt], a[mt][0], a[mt][1], a[mt][2], a[mt][3],
                                 b[nt][0], b[nt][1]);
            }
        }
    }
#undef ISSUE_STAGE

    // ---------------- Epilogue: dequant scale + bias ----------------
    const float sc = __ldg(in_scale) * __ldg(w_scale);
    const int gid = lane >> 2;
    const int tig = lane & 3;

    float2 bv[4];
#pragma unroll
    for (int nt = 0; nt < 4; nt++)
        bv[nt] = *reinterpret_cast<const float2*>(bias + n0 + warp_n * 32 + nt * 8 + 2 * tig);

#pragma unroll
    for (int mt = 0; mt < 4; mt++) {
        const int row = m0 + warp_m * 64 + mt * 16 + gid;
#pragma unroll
        for (int nt = 0; nt < 4; nt++) {
            const int col = n0 + warp_n * 32 + nt * 8 + 2 * tig;
            float2 o0, o1;
            o0.x = acc[mt][nt][0] * sc + bv[nt].x;
            o0.y = acc[mt][nt][1] * sc + bv[nt].y;
            o1.x = acc[mt][nt][2] * sc + bv[nt].x;
            o1.y = acc[mt][nt][3] * sc + bv[nt].y;
            *reinterpret_cast<float2*>(out + (size_t)row * N_TOTAL + col) = o0;
            *reinterpret_cast<float2*>(out + (size_t)(row + 8) * N_TOTAL + col) = o1;
        }
    }
}

// ---------------------------------------------------------------------------
// Launch
// ---------------------------------------------------------------------------
extern "C" void kernel_launch(void* const* d_in, const int* in_sizes, int n_in,
                              void* d_out, int out_size) {
    const float* x = nullptr;
    const void* qweight = nullptr;
    const float* bias = nullptr;
    const float* s_first = nullptr;
    const float* s_second = nullptr;
    int x_idx = -1;

    for (int i = 0; i < n_in; i++) {
        long long sz = in_sizes[i];
        if (sz == (long long)M_TOTAL * K_TOTAL) { x = (const float*)d_in[i]; x_idx = i; }
        else if (sz == (long long)N_TOTAL * K_TOTAL) qweight = d_in[i];
        else if (sz == N_TOTAL) bias = (const float*)d_in[i];
        else if (sz == 1) { if (!s_first) s_first = (const float*)d_in[i];
                            else s_second = (const float*)d_in[i]; }
    }
    const float* wscale = (x_idx == 0) ? s_first : s_second;
    const float* iscale = (x_idx == 0) ? s_second : s_first;
    float* out = (float*)d_out;

    fp8lin_detect<<<1, 256>>>(qweight);
    const size_t total = (size_t)M_TOTAL * K_TOTAL;
    fp8lin_quant<<<(unsigned)(total / (16 * 256)), 256>>>(x, iscale);
    fp8lin_wconv<<<(unsigned)((size_t)N_TOTAL * K_TOTAL / (16 * 256)), 256>>>(qweight);

    cudaFuncSetAttribute(fp8lin_gemm, cudaFuncAttributeMaxDynamicSharedMemorySize, SMEM_DYN);
    dim3 grid(N_TOTAL / BN, M_TOTAL / BM);
    fp8lin_gemm<<<grid, 256, SMEM_DYN>>>(out, iscale, wscale, bias);
}

// round 7
// speedup vs baseline: 1.2368x; 1.0149x over previous
#include <cuda_runtime.h>
#include <cuda_bf16.h>
#include <cuda_fp8.h>
#include <cstdint>
#include <math.h>

#define DEV __device__ __forceinline__

// ---------------------------------------------------------------------------
// Problem constants
// ---------------------------------------------------------------------------
static constexpr int M_TOTAL = 16384;   // B*S
static constexpr int N_TOTAL = 2048;    // OUT
static constexpr int K_TOTAL = 2048;    // IN

static constexpr int BM = 128;
static constexpr int BN = 128;
static constexpr int BK = 128;                   // fp8 bytes per K-chunk (full row)
static constexpr int NUM_CHUNKS = K_TOTAL / BK;  // 16
static constexpr int STAGES = 3;
static constexpr int RS = 144;                   // padded row stride (128 + 16)
static constexpr int B_OFF = BM * RS;            // 18432
static constexpr int STAGE_BYTES = (BM + BN) * RS;      // 36864
static constexpr int SMEM_DYN = STAGES * STAGE_BYTES;   // 110592 -> 2 CTAs/SM (221KB)

// ---------------------------------------------------------------------------
// Scratch
// ---------------------------------------------------------------------------
__device__ uint8_t g_A[(size_t)M_TOTAL * K_TOTAL];   // 32 MB
__device__ uint8_t g_B[(size_t)N_TOTAL * K_TOTAL];   // 4 MB
__device__ int g_mode;   // qweight dtype: 0 = f32 codes, 1 = bf16 codes, 2 = raw bytes

// ---------------------------------------------------------------------------
// PTX helpers
// ---------------------------------------------------------------------------
DEV uint32_t smem_u32(const void* p) {
    uint32_t a;
    asm("{ .reg .u64 t; cvta.to.shared.u64 t, %1; cvt.u32.u64 %0, t; }" : "=r"(a) : "l"(p));
    return a;
}

#define LDSM_X4(r0, r1, r2, r3, addr) \
    asm volatile("ldmatrix.sync.aligned.m8n8.x4.shared.b16 {%0,%1,%2,%3}, [%4];" \
                 : "=r"(r0), "=r"(r1), "=r"(r2), "=r"(r3) : "r"(addr))

// fp8 e4m3 MMA (validated R5/R6)
#define MMA_E4M3(c, a0, a1, a2, a3, b0, b1) \
    asm volatile("mma.sync.aligned.m16n8k32.row.col.f32.e4m3.e4m3.f32 " \
                 "{%0,%1,%2,%3}, {%4,%5,%6,%7}, {%8,%9}, {%0,%1,%2,%3};" \
                 : "+f"((c)[0]), "+f"((c)[1]), "+f"((c)[2]), "+f"((c)[3]) \
                 : "r"(a0), "r"(a1), "r"(a2), "r"(a3), "r"(b0), "r"(b1))

#define CP_ASYNC_16(dst, src) \
    asm volatile("cp.async.cg.shared.global [%0], [%1], 16;" :: "r"(dst), "l"(src))

DEV bool e4m3_exact(float v) {
    if (!isfinite(v) || fabsf(v) > 448.0f) return false;
    __nv_fp8_e4m3 e(v);
    return (float)e == v;
}

// ---------------------------------------------------------------------------
// Kernel 0: probe qweight dtype (f32 tested before bf16)
// ---------------------------------------------------------------------------
__global__ void fp8lin_detect(const void* qw) {
    __shared__ int ok32s, okbfs;
    const int t = threadIdx.x;
    if (t == 0) { ok32s = 1; okbfs = 1; }
    __syncthreads();

    const float* f = (const float*)qw;
    const unsigned short* hb = (const unsigned short*)qw;
    bool ok32 = true, okbf = true;
#pragma unroll
    for (int j = 0; j < 4; j++)
        if (!e4m3_exact(f[t * 4 + j])) ok32 = false;
#pragma unroll
    for (int j = 0; j < 8; j++)
        if (!e4m3_exact(__bfloat162float(__ushort_as_bfloat16(hb[t * 8 + j])))) okbf = false;

    if (!ok32) ok32s = 0;
    if (!okbf) okbfs = 0;
    __syncthreads();
    if (t == 0) g_mode = ok32s ? 0 : (okbfs ? 1 : 2);
}

// ---------------------------------------------------------------------------
// Kernel 1: x -> e4m3 bytes, 16 elems/thread
// ---------------------------------------------------------------------------
__global__ void __launch_bounds__(256) fp8lin_quant(const float* __restrict__ x,
                                                    const float* __restrict__ in_scale) {
    const float r = 1.0f / __ldg(in_scale);
    const size_t i = ((size_t)blockIdx.x * blockDim.x + threadIdx.x) * 16;
    const float4* src = reinterpret_cast<const float4*>(x + i);

    unsigned short h[8];
#pragma unroll
    for (int j = 0; j < 4; j++) {
        float4 v = src[j];
        float2 p0 = make_float2(v.x * r, v.y * r);
        float2 p1 = make_float2(v.z * r, v.w * r);
        h[2 * j + 0] = (unsigned short)__nv_cvt_float2_to_fp8x2(p0, __NV_SATFINITE, __NV_E4M3);
        h[2 * j + 1] = (unsigned short)__nv_cvt_float2_to_fp8x2(p1, __NV_SATFINITE, __NV_E4M3);
    }
    uint4 o;
    o.x = (uint32_t)h[0] | ((uint32_t)h[1] << 16);
    o.y = (uint32_t)h[2] | ((uint32_t)h[3] << 16);
    o.z = (uint32_t)h[4] | ((uint32_t)h[5] << 16);
    o.w = (uint32_t)h[6] | ((uint32_t)h[7] << 16);
    *reinterpret_cast<uint4*>(&g_A[i]) = o;
}

// ---------------------------------------------------------------------------
// Kernel 2: qweight -> e4m3 bytes (3 dtype modes)
// ---------------------------------------------------------------------------
__global__ void __launch_bounds__(256) fp8lin_wconv(const void* __restrict__ qw) {
    const int mode = g_mode;
    const size_t i = ((size_t)blockIdx.x * blockDim.x + threadIdx.x) * 16;

    uint4 o;
    if (mode == 0) {                       // float32 code values (expected)
        const float4* s = reinterpret_cast<const float4*>((const float*)qw + i);
        unsigned short h[8];
#pragma unroll
        for (int j = 0; j < 4; j++) {
            float4 v = s[j];
            float2 p0 = make_float2(v.x, v.y);
            float2 p1 = make_float2(v.z, v.w);
            h[2 * j + 0] = (unsigned short)__nv_cvt_float2_to_fp8x2(p0, __NV_SATFINITE, __NV_E4M3);
            h[2 * j + 1] = (unsigned short)__nv_cvt_float2_to_fp8x2(p1, __NV_SATFINITE, __NV_E4M3);
        }
        o.x = (uint32_t)h[0] | ((uint32_t)h[1] << 16);
        o.y = (uint32_t)h[2] | ((uint32_t)h[3] << 16);
        o.z = (uint32_t)h[4] | ((uint32_t)h[5] << 16);
        o.w = (uint32_t)h[6] | ((uint32_t)h[7] << 16);
    } else if (mode == 2) {                // raw e4m3 bytes
        o = *reinterpret_cast<const uint4*>((const uint8_t*)qw + i);
    } else {                               // bf16 codes
        const unsigned short* s = (const unsigned short*)qw + i;
        unsigned short h[8];
#pragma unroll
        for (int j = 0; j < 8; j++) {
            float2 p = make_float2(__bfloat162float(__ushort_as_bfloat16(s[2 * j])),
                                   __bfloat162float(__ushort_as_bfloat16(s[2 * j + 1])));
            h[j] = (unsigned short)__nv_cvt_float2_to_fp8x2(p, __NV_SATFINITE, __NV_E4M3);
        }
        o.x = (uint32_t)h[0] | ((uint32_t)h[1] << 16);
        o.y = (uint32_t)h[2] | ((uint32_t)h[3] << 16);
        o.z = (uint32_t)h[4] | ((uint32_t)h[5] << 16);
        o.w = (uint32_t)h[6] | ((uint32_t)h[7] << 16);
    }
    *reinterpret_cast<uint4*>(&g_B[i]) = o;
}

// ---------------------------------------------------------------------------
// Kernel 3: fp8 QMMA GEMM — BK=128, 3 stages, fully unrolled chunk loop
// ---------------------------------------------------------------------------
__global__ void __launch_bounds__(256, 2) fp8lin_gemm(float* __restrict__ out,
                                                      const float* __restrict__ in_scale,
                                                      const float* __restrict__ w_scale,
                                                      const float* __restrict__ bias) {
    extern __shared__ char dsm[];
    const uint32_t smem0 = smem_u32(dsm);

    const int tid = threadIdx.x;
    const int wid = tid >> 5;
    const int lane = tid & 31;
    const int warp_m = wid >> 2;        // 0..1 -> 64 rows
    const int warp_n = wid & 3;         // 0..3 -> 32 cols

    const int n0 = blockIdx.x * BN;     // N fastest -> A-tile L2 reuse
    const int m0 = blockIdx.y * BM;

    // ---- hoisted loader addressing: 8 src pointers, 8 const dst offsets ----
    const int brow = tid >> 3;          // 0..31
    const int seg = (tid & 7) * 16;     // 0..112
    const uint8_t* sA[4];
    const uint8_t* sB[4];
    uint32_t dA[4], dB[4];
#pragma unroll
    for (int i = 0; i < 4; i++) {
        sA[i] = g_A + (size_t)(m0 + brow + 32 * i) * K_TOTAL + seg;
        sB[i] = g_B + (size_t)(n0 + brow + 32 * i) * K_TOTAL + seg;
        dA[i] = (uint32_t)((brow + 32 * i) * RS + seg);
        dB[i] = (uint32_t)(B_OFF + (brow + 32 * i) * RS + seg);
    }

#define ISSUE_STAGE(stage_base) do { \
        CP_ASYNC_16((stage_base) + dA[0], sA[0]); \
        CP_ASYNC_16((stage_base) + dA[1], sA[1]); \
        CP_ASYNC_16((stage_base) + dA[2], sA[2]); \
        CP_ASYNC_16((stage_base) + dA[3], sA[3]); \
        CP_ASYNC_16((stage_base) + dB[0], sB[0]); \
        CP_ASYNC_16((stage_base) + dB[1], sB[1]); \
        CP_ASYNC_16((stage_base) + dB[2], sB[2]); \
        CP_ASYNC_16((stage_base) + dB[3], sB[3]); \
        sA[0] += BK; sA[1] += BK; sA[2] += BK; sA[3] += BK; \
        sB[0] += BK; sB[1] += BK; sB[2] += BK; sB[3] += BK; \
        asm volatile("cp.async.commit_group;"); \
    } while (0)

    // ---- ldmatrix bases (validated R6) ----
    const int amat = lane >> 3;
    const uint32_t a_base = smem0
        + (uint32_t)((warp_m * 64 + (amat & 1) * 8 + (lane & 7)) * RS + (amat >> 1) * 16);
    const uint32_t b_base = smem0 + (uint32_t)(B_OFF
        + (warp_n * 32 + ((lane >> 4) * 8) + (lane & 7)) * RS + ((lane >> 3) & 1) * 16);

    float acc[4][4][4];
#pragma unroll
    for (int mt = 0; mt < 4; mt++)
#pragma unroll
        for (int nt = 0; nt < 4; nt++)
#pragma unroll
            for (int q = 0; q < 4; q++) acc[mt][nt][q] = 0.0f;

    // Prefill stages 0,1 with chunks 0,1
    ISSUE_STAGE(smem0 + 0 * STAGE_BYTES);
    ISSUE_STAGE(smem0 + 1 * STAGE_BYTES);

#pragma unroll
    for (int c = 0; c < NUM_CHUNKS; c++) {
        // Oldest outstanding groups at this point: {c, c+1}. Need chunk c done.
        if (c < NUM_CHUNKS - 1)
            asm volatile("cp.async.wait_group 1;");
        else
            asm volatile("cp.async.wait_group 0;");
        __syncthreads();   // data visible to all; all warps done reading stage (c+2)%3

        if (c + 2 < NUM_CHUNKS)
            ISSUE_STAGE(smem0 + (uint32_t)(((c + 2) % STAGES) * STAGE_BYTES));

        const uint32_t soff = (uint32_t)((c % STAGES) * STAGE_BYTES);  // literal
#pragma unroll
        for (int ks = 0; ks < 4; ks++) {
            uint32_t a[4][4], b[4][2];
#pragma unroll
            for (int mt = 0; mt < 4; mt++)
                LDSM_X4(a[mt][0], a[mt][1], a[mt][2], a[mt][3],
                        a_base + soff + (uint32_t)(mt * 16 * RS + ks * 32));
#pragma unroll
            for (int p = 0; p < 2; p++)
                LDSM_X4(b[2 * p][0], b[2 * p][1], b[2 * p + 1][0], b[2 * p + 1][1],
                        b_base + soff + (uint32_t)(p * 16 * RS + ks * 32));
#pragma unroll
            for (int mt = 0; mt < 4; mt++)
#pragma unroll
                for (int nt = 0; nt < 4; nt++)
                    MMA_E4M3(acc[mt][nt], a[mt][0], a[mt][1], a[mt][2], a[mt][3],
                             b[nt][0], b[nt][1]);
        }
    }
#undef ISSUE_STAGE

    // ---------------- Epilogue: dequant scale + bias ----------------
    const float sc = __ldg(in_scale) * __ldg(w_scale);
    const int gid = lane >> 2;
    const int tig = lane & 3;

    float2 bv[4];
#pragma unroll
    for (int nt = 0; nt < 4; nt++)
        bv[nt] = *reinterpret_cast<const float2*>(bias + n0 + warp_n * 32 + nt * 8 + 2 * tig);

#pragma unroll
    for (int mt = 0; mt < 4; mt++) {
        const int row = m0 + warp_m * 64 + mt * 16 + gid;
#pragma unroll
        for (int nt = 0; nt < 4; nt++) {
            const int col = n0 + warp_n * 32 + nt * 8 + 2 * tig;
            float2 o0, o1;
            o0.x = acc[mt][nt][0] * sc + bv[nt].x;
            o0.y = acc[mt][nt][1] * sc + bv[nt].y;
            o1.x = acc[mt][nt][2] * sc + bv[nt].x;
            o1.y = acc[mt][nt][3] * sc + bv[nt].y;
            *reinterpret_cast<float2*>(out + (size_t)row * N_TOTAL + col) = o0;
            *reinterpret_cast<float2*>(out + (size_t)(row + 8) * N_TOTAL + col) = o1;
        }
    }
}

// ---------------------------------------------------------------------------
// Launch
// ---------------------------------------------------------------------------
extern "C" void kernel_launch(void* const* d_in, const int* in_sizes, int n_in,
                              void* d_out, int out_size) {
    const float* x = nullptr;
    const void* qweight = nullptr;
    const float* bias = nullptr;
    const float* s_first = nullptr;
    const float* s_second = nullptr;
    int x_idx = -1;

    for (int i = 0; i < n_in; i++) {
        long long sz = in_sizes[i];
        if (sz == (long long)M_TOTAL * K_TOTAL) { x = (const float*)d_in[i]; x_idx = i; }
        else if (sz == (long long)N_TOTAL * K_TOTAL) qweight = d_in[i];
        else if (sz == N_TOTAL) bias = (const float*)d_in[i];
        else if (sz == 1) { if (!s_first) s_first = (const float*)d_in[i];
                            else s_second = (const float*)d_in[i]; }
    }
    const float* wscale = (x_idx == 0) ? s_first : s_second;
    const float* iscale = (x_idx == 0) ? s_second : s_first;
    float* out = (float*)d_out;

    fp8lin_detect<<<1, 256>>>(qweight);
    const size_t total = (size_t)M_TOTAL * K_TOTAL;
    fp8lin_quant<<<(unsigned)(total / (16 * 256)), 256>>>(x, iscale);
    fp8lin_wconv<<<(unsigned)((size_t)N_TOTAL * K_TOTAL / (16 * 256)), 256>>>(qweight);

    cudaFuncSetAttribute(fp8lin_gemm, cudaFuncAttributeMaxDynamicSharedMemorySize, SMEM_DYN);
    dim3 grid(N_TOTAL / BN, M_TOTAL / BM);
    fp8lin_gemm<<<grid, 256, SMEM_DYN>>>(out, iscale, wscale, bias);
}